// round 2
// baseline (speedup 1.0000x reference)
#include <cuda_runtime.h>
#include <cuda_fp16.h>
#include <math.h>
#include <stdint.h>

// Problem dims
// tokens [2048,80] i32, emb [10000,100] f32, Wx0 [100,256], Wx1 [256,256],
// Wh [2,256,256], b [2,256], h0 [2,2048,256], Wo [256,1], bo [1]
// out [2048,1] f32

#define T_ 80
#define BS_ 2048
#define U_ 256
#define E_ 100
#define EP_ 112       // E padded to multiple of 16
#define V_ 10000

#define WPAD 264      // smem k-stride for 256-wide weights (conflict-free ldmatrix)
#define EPS_ 120      // smem k-stride for 112-wide

// ---------------- scratch (device globals; no allocs allowed) ----------------
__device__ __half g_emb16[V_ * EP_];           // 2.24 MB
__device__ __half g_Wx0T[U_ * EP_];            // [u_out][e]
__device__ __half g_WT0[U_ * U_];              // Wh0^T [n][k]
__device__ __half g_WT1[U_ * U_];              // Wx1^T [n][k]
__device__ __half g_WT2[U_ * U_];              // Wh1^T [n][k]
__device__ __half g_X0[(size_t)T_ * BS_ * U_]; // 84 MB  (x@Wx0 + b0, fp16)
__device__ __half g_H0[(size_t)T_ * BS_ * U_]; // 84 MB  (layer0 hidden states)
__device__ float  g_Z1[(size_t)T_ * BS_ * U_]; // 168 MB (H0@Wx1 + b1, fp32)

// ---------------- mma helpers ----------------
__device__ __forceinline__ void ldsm4(uint32_t &r0, uint32_t &r1, uint32_t &r2,
                                      uint32_t &r3, uint32_t addr) {
    asm volatile("ldmatrix.sync.aligned.m8n8.x4.shared.b16 {%0,%1,%2,%3}, [%4];\n"
                 : "=r"(r0), "=r"(r1), "=r"(r2), "=r"(r3) : "r"(addr));
}

__device__ __forceinline__ void mma16816(float c[4], uint32_t a0, uint32_t a1,
                                         uint32_t a2, uint32_t a3,
                                         uint32_t b0, uint32_t b1) {
    asm volatile(
        "mma.sync.aligned.m16n8k16.row.col.f32.f16.f16.f32 "
        "{%0,%1,%2,%3},{%4,%5,%6,%7},{%8,%9},{%0,%1,%2,%3};\n"
        : "+f"(c[0]), "+f"(c[1]), "+f"(c[2]), "+f"(c[3])
        : "r"(a0), "r"(a1), "r"(a2), "r"(a3), "r"(b0), "r"(b1));
}

// ---------------- K0: prep (fp16 convert + transpose) ----------------
__global__ void k_prep(const float* __restrict__ emb, const float* __restrict__ Wx0,
                       const float* __restrict__ Wx1, const float* __restrict__ Wh) {
    int i = blockIdx.x * 256 + threadIdx.x;
    if (i < V_ * EP_) {
        int v = i / EP_, e = i - v * EP_;
        g_emb16[i] = __float2half(e < E_ ? emb[v * E_ + e] : 0.0f);
    }
    if (i < U_ * U_) {
        int n = i >> 8, k = i & 255;
        g_WT0[i] = __float2half(Wh[k * U_ + n]);
        g_WT1[i] = __float2half(Wx1[k * U_ + n]);
        g_WT2[i] = __float2half(Wh[U_ * U_ + k * U_ + n]);
    }
    if (i < U_ * EP_) {
        int u = i / EP_, e = i - u * EP_;
        g_Wx0T[i] = __float2half(e < E_ ? Wx0[e * U_ + u] : 0.0f);
    }
}

// ---------------- K1: X0 = emb[tok] @ Wx0 + b0 ----------------
// grid (128 batch-blocks, 8 t-groups), 256 thr. Each CTA: 16 rows x 10 timesteps.
__global__ void k_x0(const int* __restrict__ tokens, const float* __restrict__ bias) {
    extern __shared__ __half sm[];
    __half* Wsm = sm;             // 256 x 120
    __half* Asm = sm + 256 * EPS_;// 16 x 120
    const int tid = threadIdx.x;
    const int m0 = blockIdx.x * 16;
    // stage Wx0T
    for (int i8 = tid; i8 < U_ * EP_ / 8; i8 += 256) {
        int r = i8 / 14, c8 = i8 - r * 14;
        *(uint4*)(Wsm + r * EPS_ + c8 * 8) = *(const uint4*)(g_Wx0T + r * EP_ + c8 * 8);
    }
    const int lane = tid & 31, warp = tid >> 5;
    const int n0 = warp * 32;
    const uint32_t a_off = (uint32_t)__cvta_generic_to_shared(Asm) +
                           ((lane & 15) * EPS_ + (lane >> 4) * 8) * 2;
    const uint32_t wbase = (uint32_t)__cvta_generic_to_shared(Wsm);
    const int r = lane >> 2;

    for (int tt = 0; tt < 10; ++tt) {
        int t = blockIdx.y * 10 + tt;
        __syncthreads();
        if (tid < 224) {
            int m = tid / 14, c8 = tid - m * 14;
            int tok = tokens[(m0 + m) * T_ + t];
            *(uint4*)(Asm + m * EPS_ + c8 * 8) =
                *(const uint4*)(g_emb16 + (size_t)tok * EP_ + c8 * 8);
        }
        __syncthreads();
        float acc[4][4] = {};
#pragma unroll
        for (int ks = 0; ks < 7; ++ks) {
            uint32_t a0, a1, a2, a3;
            ldsm4(a0, a1, a2, a3, a_off + ks * 32);
#pragma unroll
            for (int p = 0; p < 2; ++p) {
                uint32_t b0, b1, b2, b3;
                ldsm4(b0, b1, b2, b3,
                      wbase + ((n0 + p * 16 + (lane & 15)) * EPS_ + ks * 16 +
                               (lane >> 4) * 8) * 2);
                mma16816(acc[2 * p],     a0, a1, a2, a3, b0, b2);
                mma16816(acc[2 * p + 1], a0, a1, a2, a3, b1, b3);
            }
        }
#pragma unroll
        for (int j = 0; j < 4; ++j) {
            int col = n0 + j * 8 + (lane & 3) * 2;
            float bi0 = bias[col], bi1 = bias[col + 1];
            size_t base = ((size_t)t * BS_ + m0 + r) * U_ + col;
            *(__half2*)(g_X0 + base) = __floats2half2_rn(acc[j][0] + bi0, acc[j][1] + bi1);
            *(__half2*)(g_X0 + base + 8 * U_) = __floats2half2_rn(acc[j][2] + bi0, acc[j][3] + bi1);
        }
    }
}

// ---------------- K2: layer-0 recurrence ----------------
// grid 128, 256 thr. h0_t = tanh(X0[t] + h0 @ Wh0); stream H0 (fp16).
__global__ void k_r0(const float* __restrict__ h0in) {
    extern __shared__ __half sm[];
    __half* Wsm = sm;                              // 256 x 264
    __half* hb0 = sm + U_ * WPAD;                  // 16 x 264 (double buffer)
    __half* hb1 = hb0 + 16 * WPAD;
    const int tid = threadIdx.x;
    const int m0 = blockIdx.x * 16;
    for (int i8 = tid; i8 < U_ * U_ / 8; i8 += 256) {
        int rr = i8 >> 5, c8 = i8 & 31;
        *(uint4*)(Wsm + rr * WPAD + c8 * 8) = *(const uint4*)(g_WT0 + rr * U_ + c8 * 8);
    }
    for (int i2 = tid; i2 < 16 * U_ / 2; i2 += 256) {
        int m = i2 >> 7, u2 = i2 & 127;
        float2 v = *(const float2*)(h0in + (size_t)(m0 + m) * U_ + u2 * 2);
        *(__half2*)(hb0 + m * WPAD + u2 * 2) = __floats2half2_rn(v.x, v.y);
    }
    __syncthreads();

    const int lane = tid & 31, warp = tid >> 5;
    const int n0 = warp * 32;
    const uint32_t wbase = (uint32_t)__cvta_generic_to_shared(Wsm);
    const uint32_t hoff = ((lane & 15) * WPAD + (lane >> 4) * 8) * 2;
    const uint32_t hs0 = (uint32_t)__cvta_generic_to_shared(hb0);
    const uint32_t hs1 = (uint32_t)__cvta_generic_to_shared(hb1);
    const int r = lane >> 2;

    for (int t = 0; t < T_; ++t) {
        // prefetch additive term (hides DRAM latency behind MMA)
        __half2 x0v[4][2];
#pragma unroll
        for (int j = 0; j < 4; ++j) {
            int col = n0 + j * 8 + (lane & 3) * 2;
            size_t base = ((size_t)t * BS_ + m0 + r) * U_ + col;
            x0v[j][0] = *(const __half2*)(g_X0 + base);
            x0v[j][1] = *(const __half2*)(g_X0 + base + 8 * U_);
        }
        uint32_t ha = ((t & 1) ? hs1 : hs0) + hoff;
        float acc[4][4] = {};
#pragma unroll
        for (int ks = 0; ks < 16; ++ks) {
            uint32_t a0, a1, a2, a3;
            ldsm4(a0, a1, a2, a3, ha + ks * 32);
#pragma unroll
            for (int p = 0; p < 2; ++p) {
                uint32_t b0, b1, b2, b3;
                ldsm4(b0, b1, b2, b3,
                      wbase + ((n0 + p * 16 + (lane & 15)) * WPAD + ks * 16 +
                               (lane >> 4) * 8) * 2);
                mma16816(acc[2 * p],     a0, a1, a2, a3, b0, b2);
                mma16816(acc[2 * p + 1], a0, a1, a2, a3, b1, b3);
            }
        }
        __half* hn = (t & 1) ? hb0 : hb1;
#pragma unroll
        for (int j = 0; j < 4; ++j) {
            int col = n0 + j * 8 + (lane & 3) * 2;
            float2 xa = __half22float2(x0v[j][0]);
            float2 xb = __half22float2(x0v[j][1]);
            float v0 = tanhf(acc[j][0] + xa.x);
            float v1 = tanhf(acc[j][1] + xa.y);
            float v2 = tanhf(acc[j][2] + xb.x);
            float v3 = tanhf(acc[j][3] + xb.y);
            __half2 p0 = __floats2half2_rn(v0, v1);
            __half2 p1 = __floats2half2_rn(v2, v3);
            *(__half2*)(hn + r * WPAD + col) = p0;
            *(__half2*)(hn + (r + 8) * WPAD + col) = p1;
            size_t base = ((size_t)t * BS_ + m0 + r) * U_ + col;
            *(__half2*)(g_H0 + base) = p0;
            *(__half2*)(g_H0 + base + 8 * U_) = p1;
        }
        __syncthreads();
    }
}

// ---------------- K3: Z1 = H0 @ Wx1 + b1 (parallel over t) ----------------
// grid (128 batch-blocks, 5 t-groups), 256 thr; each CTA does 16 timesteps.
__global__ void k_z1(const float* __restrict__ bias) {
    extern __shared__ __half sm[];
    __half* Wsm = sm;              // 256 x 264 (Wx1^T)
    __half* Asm = sm + U_ * WPAD;  // 16 x 264
    const int tid = threadIdx.x;
    const int m0 = blockIdx.x * 16;
    for (int i8 = tid; i8 < U_ * U_ / 8; i8 += 256) {
        int rr = i8 >> 5, c8 = i8 & 31;
        *(uint4*)(Wsm + rr * WPAD + c8 * 8) = *(const uint4*)(g_WT1 + rr * U_ + c8 * 8);
    }
    const int lane = tid & 31, warp = tid >> 5;
    const int n0 = warp * 32;
    const uint32_t wbase = (uint32_t)__cvta_generic_to_shared(Wsm);
    const uint32_t a_off = (uint32_t)__cvta_generic_to_shared(Asm) +
                           ((lane & 15) * WPAD + (lane >> 4) * 8) * 2;
    const int r = lane >> 2;

    for (int tt = 0; tt < 16; ++tt) {
        int t = blockIdx.y * 16 + tt;
        __syncthreads();
        for (int i8 = tid; i8 < 16 * U_ / 8; i8 += 256) {
            int m = i8 >> 5, c8 = i8 & 31;
            *(uint4*)(Asm + m * WPAD + c8 * 8) =
                *(const uint4*)(g_H0 + ((size_t)t * BS_ + m0 + m) * U_ + c8 * 8);
        }
        __syncthreads();
        float acc[4][4] = {};
#pragma unroll
        for (int ks = 0; ks < 16; ++ks) {
            uint32_t a0, a1, a2, a3;
            ldsm4(a0, a1, a2, a3, a_off + ks * 32);
#pragma unroll
            for (int p = 0; p < 2; ++p) {
                uint32_t b0, b1, b2, b3;
                ldsm4(b0, b1, b2, b3,
                      wbase + ((n0 + p * 16 + (lane & 15)) * WPAD + ks * 16 +
                               (lane >> 4) * 8) * 2);
                mma16816(acc[2 * p],     a0, a1, a2, a3, b0, b2);
                mma16816(acc[2 * p + 1], a0, a1, a2, a3, b1, b3);
            }
        }
#pragma unroll
        for (int j = 0; j < 4; ++j) {
            int col = n0 + j * 8 + (lane & 3) * 2;
            float bi0 = bias[U_ + col], bi1 = bias[U_ + col + 1];
            size_t base = ((size_t)t * BS_ + m0 + r) * U_ + col;
            *(float2*)(g_Z1 + base) = make_float2(acc[j][0] + bi0, acc[j][1] + bi1);
            *(float2*)(g_Z1 + base + 8 * U_) = make_float2(acc[j][2] + bi0, acc[j][3] + bi1);
        }
    }
}

// ---------------- K4: layer-1 recurrence + fused head ----------------
__global__ void k_r1(const float* __restrict__ h0in, const float* __restrict__ Wo,
                     const float* __restrict__ bo, float* __restrict__ out) {
    extern __shared__ __half sm[];
    __half* Wsm = sm;                 // 256 x 264 (Wh1^T)
    __half* hb0 = sm + U_ * WPAD;
    __half* hb1 = hb0 + 16 * WPAD;
    __shared__ float zs[16];
    const int tid = threadIdx.x;
    const int m0 = blockIdx.x * 16;
    if (tid < 16) zs[tid] = 0.0f;
    for (int i8 = tid; i8 < U_ * U_ / 8; i8 += 256) {
        int rr = i8 >> 5, c8 = i8 & 31;
        *(uint4*)(Wsm + rr * WPAD + c8 * 8) = *(const uint4*)(g_WT2 + rr * U_ + c8 * 8);
    }
    for (int i2 = tid; i2 < 16 * U_ / 2; i2 += 256) {
        int m = i2 >> 7, u2 = i2 & 127;
        float2 v = *(const float2*)(h0in + (size_t)BS_ * U_ + (size_t)(m0 + m) * U_ + u2 * 2);
        *(__half2*)(hb0 + m * WPAD + u2 * 2) = __floats2half2_rn(v.x, v.y);
    }
    __syncthreads();

    const int lane = tid & 31, warp = tid >> 5;
    const int n0 = warp * 32;
    const uint32_t wbase = (uint32_t)__cvta_generic_to_shared(Wsm);
    const uint32_t hoff = ((lane & 15) * WPAD + (lane >> 4) * 8) * 2;
    const uint32_t hs0 = (uint32_t)__cvta_generic_to_shared(hb0);
    const uint32_t hs1 = (uint32_t)__cvta_generic_to_shared(hb1);
    const int r = lane >> 2;

    for (int t = 0; t < T_; ++t) {
        float2 zv[4][2];
#pragma unroll
        for (int j = 0; j < 4; ++j) {
            int col = n0 + j * 8 + (lane & 3) * 2;
            size_t base = ((size_t)t * BS_ + m0 + r) * U_ + col;
            zv[j][0] = *(const float2*)(g_Z1 + base);
            zv[j][1] = *(const float2*)(g_Z1 + base + 8 * U_);
        }
        uint32_t ha = ((t & 1) ? hs1 : hs0) + hoff;
        float acc[4][4] = {};
#pragma unroll
        for (int ks = 0; ks < 16; ++ks) {
            uint32_t a0, a1, a2, a3;
            ldsm4(a0, a1, a2, a3, ha + ks * 32);
#pragma unroll
            for (int p = 0; p < 2; ++p) {
                uint32_t b0, b1, b2, b3;
                ldsm4(b0, b1, b2, b3,
                      wbase + ((n0 + p * 16 + (lane & 15)) * WPAD + ks * 16 +
                               (lane >> 4) * 8) * 2);
                mma16816(acc[2 * p],     a0, a1, a2, a3, b0, b2);
                mma16816(acc[2 * p + 1], a0, a1, a2, a3, b1, b3);
            }
        }
        __half* hn = (t & 1) ? hb0 : hb1;
#pragma unroll
        for (int j = 0; j < 4; ++j) {
            int col = n0 + j * 8 + (lane & 3) * 2;
            float v0 = tanhf(acc[j][0] + zv[j][0].x);
            float v1 = tanhf(acc[j][1] + zv[j][0].y);
            float v2 = tanhf(acc[j][2] + zv[j][1].x);
            float v3 = tanhf(acc[j][3] + zv[j][1].y);
            *(__half2*)(hn + r * WPAD + col) = __floats2half2_rn(v0, v1);
            *(__half2*)(hn + (r + 8) * WPAD + col) = __floats2half2_rn(v2, v3);
            if (t == T_ - 1) {
                float w0 = __ldg(Wo + col), w1 = __ldg(Wo + col + 1);
                atomicAdd(&zs[r],     v0 * w0 + v1 * w1);
                atomicAdd(&zs[r + 8], v2 * w0 + v3 * w1);
            }
        }
        __syncthreads();
    }
    if (tid < 16) {
        float z = zs[tid] + bo[0];
        out[m0 + tid] = 1.0f / (1.0f + expf(-z));
    }
}

// ---------------- launcher ----------------
extern "C" void kernel_launch(void* const* d_in, const int* in_sizes, int n_in,
                              void* d_out, int out_size) {
    const int*   tokens = (const int*)  d_in[0];
    const float* emb    = (const float*)d_in[1];
    const float* Wx0    = (const float*)d_in[2];
    const float* Wx1    = (const float*)d_in[3];
    const float* Wh     = (const float*)d_in[4];
    const float* b      = (const float*)d_in[5];
    const float* h0     = (const float*)d_in[6];
    const float* Wo     = (const float*)d_in[7];
    const float* bo     = (const float*)d_in[8];
    float* out = (float*)d_out;

    const int smem_x0 = (256 * EPS_ + 16 * EPS_) * 2;           // 65280
    const int smem_r  = (U_ * WPAD + 32 * WPAD) * 2;            // 152064
    const int smem_z  = (U_ * WPAD + 16 * WPAD) * 2;            // 143616
    cudaFuncSetAttribute(k_x0, cudaFuncAttributeMaxDynamicSharedMemorySize, smem_x0);
    cudaFuncSetAttribute(k_r0, cudaFuncAttributeMaxDynamicSharedMemorySize, smem_r);
    cudaFuncSetAttribute(k_z1, cudaFuncAttributeMaxDynamicSharedMemorySize, smem_z);
    cudaFuncSetAttribute(k_r1, cudaFuncAttributeMaxDynamicSharedMemorySize, smem_r);

    k_prep<<<(V_ * EP_ + 255) / 256, 256>>>(emb, Wx0, Wx1, Wh);
    dim3 g1(128, 8);
    k_x0<<<g1, 256, smem_x0>>>(tokens, b);
    k_r0<<<128, 256, smem_r>>>(h0);
    dim3 g3(128, 5);
    k_z1<<<g3, 256, smem_z>>>(b);
    k_r1<<<128, 256, smem_r>>>(h0, Wo, bo, out);
}

// round 4
// speedup vs baseline: 1.4761x; 1.4761x over previous
#include <cuda_runtime.h>
#include <cuda_fp16.h>
#include <math.h>
#include <stdint.h>

// dims: tokens [2048,80] i32, emb [10000,100] f32, Wx0 [100,256], Wx1 [256,256],
// Wh [2,256,256], b [2,256], h0 [2,2048,256], Wo [256,1], bo [1] -> out [2048,1] f32

#define T_ 80
#define BS_ 2048
#define U_ 256
#define E_ 100
#define EP_ 112
#define V_ 10000

#define WPAD 264      // smem k-stride for 256-wide (conflict-free ldmatrix)
#define EPS_ 120      // smem k-stride for 112-wide

// ---------------- scratch ----------------
__device__ __half g_emb16[V_ * EP_];
__device__ __half g_Wx0T[U_ * EP_];
__device__ __half g_WT0[U_ * U_];              // Wh0^T [n][k]
__device__ __half g_WT1[U_ * U_];              // Wx1^T [n][k]
__device__ __half g_WT2[U_ * U_];              // Wh1^T [n][k]
__device__ __half g_X0[(size_t)T_ * BS_ * U_];
__device__ __half g_H0[(size_t)T_ * BS_ * U_];
__device__ float  g_Z1[(size_t)T_ * BS_ * U_];

// ---------------- helpers ----------------
__device__ __forceinline__ void ldsm4(uint32_t &r0, uint32_t &r1, uint32_t &r2,
                                      uint32_t &r3, uint32_t addr) {
    asm volatile("ldmatrix.sync.aligned.m8n8.x4.shared.b16 {%0,%1,%2,%3}, [%4];\n"
                 : "=r"(r0), "=r"(r1), "=r"(r2), "=r"(r3) : "r"(addr));
}

__device__ __forceinline__ void mma16816(float c[4], uint32_t a0, uint32_t a1,
                                         uint32_t a2, uint32_t a3,
                                         uint32_t b0, uint32_t b1) {
    asm volatile(
        "mma.sync.aligned.m16n8k16.row.col.f32.f16.f16.f32 "
        "{%0,%1,%2,%3},{%4,%5,%6,%7},{%8,%9},{%0,%1,%2,%3};\n"
        : "+f"(c[0]), "+f"(c[1]), "+f"(c[2]), "+f"(c[3])
        : "r"(a0), "r"(a1), "r"(a2), "r"(a3), "r"(b0), "r"(b1));
}

__device__ __forceinline__ float ftanh(float x) {
    float e = __expf(-2.0f * fabsf(x));
    float r = __fdividef(1.0f - e, 1.0f + e);
    return copysignf(r, x);
}

// ---------------- K0: prep ----------------
__global__ void k_prep(const float* __restrict__ emb, const float* __restrict__ Wx0,
                       const float* __restrict__ Wx1, const float* __restrict__ Wh) {
    int i = blockIdx.x * 256 + threadIdx.x;
    if (i < V_ * EP_) {
        int v = i / EP_, e = i - v * EP_;
        g_emb16[i] = __float2half(e < E_ ? emb[v * E_ + e] : 0.0f);
    }
    if (i < U_ * U_) {
        int n = i >> 8, k = i & 255;
        g_WT0[i] = __float2half(Wh[k * U_ + n]);
        g_WT1[i] = __float2half(Wx1[k * U_ + n]);
        g_WT2[i] = __float2half(Wh[U_ * U_ + k * U_ + n]);
    }
    if (i < U_ * EP_) {
        int u = i / EP_, e = i - u * EP_;
        g_Wx0T[i] = __float2half(e < E_ ? Wx0[e * U_ + u] : 0.0f);
    }
}

// ---------------- K1: X0 = emb[tok] @ Wx0 + b0 ----------------
__global__ __launch_bounds__(256, 1) void k_x0(const int* __restrict__ tokens,
                                               const float* __restrict__ bias) {
    extern __shared__ __half sm[];
    __half* Wsm = sm;               // 256 x 120
    __half* Asm = sm + 256 * EPS_;  // 16 x 120
    const int tid = threadIdx.x;
    const int m0 = blockIdx.x * 16;
    for (int i8 = tid; i8 < U_ * EP_ / 8; i8 += 256) {
        int r = i8 / 14, c8 = i8 - r * 14;
        *(uint4*)(Wsm + r * EPS_ + c8 * 8) = *(const uint4*)(g_Wx0T + r * EP_ + c8 * 8);
    }
    __syncthreads();
    const int lane = tid & 31, warp = tid >> 5;
    const int n0 = warp * 32;
    const uint32_t a_off = (uint32_t)__cvta_generic_to_shared(Asm) +
                           ((lane & 15) * EPS_ + (lane >> 4) * 8) * 2;
    const uint32_t wbase = (uint32_t)__cvta_generic_to_shared(Wsm);
    const int r = lane >> 2;

    // cache B fragments in registers (7 k-chunks x 2 n16 x 4)
    uint32_t Br[7][2][4];
#pragma unroll
    for (int ks = 0; ks < 7; ++ks)
#pragma unroll
        for (int p = 0; p < 2; ++p)
            ldsm4(Br[ks][p][0], Br[ks][p][1], Br[ks][p][2], Br[ks][p][3],
                  wbase + ((n0 + p * 16 + (lane & 15)) * EPS_ + ks * 16 +
                           (lane >> 4) * 8) * 2);

    for (int tt = 0; tt < 10; ++tt) {
        int t = blockIdx.y * 10 + tt;
        __syncthreads();
        if (tid < 224) {
            int m = tid / 14, c8 = tid - m * 14;
            int tok = tokens[(m0 + m) * T_ + t];
            *(uint4*)(Asm + m * EPS_ + c8 * 8) =
                *(const uint4*)(g_emb16 + (size_t)tok * EP_ + c8 * 8);
        }
        __syncthreads();
        float acc[4][4] = {};
#pragma unroll
        for (int ks = 0; ks < 7; ++ks) {
            uint32_t a0, a1, a2, a3;
            ldsm4(a0, a1, a2, a3, a_off + ks * 32);
            mma16816(acc[0], a0, a1, a2, a3, Br[ks][0][0], Br[ks][0][2]);
            mma16816(acc[1], a0, a1, a2, a3, Br[ks][0][1], Br[ks][0][3]);
            mma16816(acc[2], a0, a1, a2, a3, Br[ks][1][0], Br[ks][1][2]);
            mma16816(acc[3], a0, a1, a2, a3, Br[ks][1][1], Br[ks][1][3]);
        }
#pragma unroll
        for (int j = 0; j < 4; ++j) {
            int col = n0 + j * 8 + (lane & 3) * 2;
            float bi0 = bias[col], bi1 = bias[col + 1];
            size_t base = ((size_t)t * BS_ + m0 + r) * U_ + col;
            *(__half2*)(g_X0 + base) = __floats2half2_rn(acc[j][0] + bi0, acc[j][1] + bi1);
            *(__half2*)(g_X0 + base + 8 * U_) = __floats2half2_rn(acc[j][2] + bi0, acc[j][3] + bi1);
        }
    }
}

// ---------------- K2: layer-0 recurrence (B in registers) ----------------
__global__ __launch_bounds__(256, 1) void k_r0(const float* __restrict__ h0in) {
    extern __shared__ __half sm[];
    __half* Wsm = sm;                   // staging only
    __half* hb0 = sm + U_ * WPAD;
    __half* hb1 = hb0 + 16 * WPAD;
    const int tid = threadIdx.x;
    const int m0 = blockIdx.x * 16;
    for (int i8 = tid; i8 < U_ * U_ / 8; i8 += 256) {
        int rr = i8 >> 5, c8 = i8 & 31;
        *(uint4*)(Wsm + rr * WPAD + c8 * 8) = *(const uint4*)(g_WT0 + rr * U_ + c8 * 8);
    }
    for (int i2 = tid; i2 < 16 * U_ / 2; i2 += 256) {
        int m = i2 >> 7, u2 = i2 & 127;
        float2 v = *(const float2*)(h0in + (size_t)(m0 + m) * U_ + u2 * 2);
        *(__half2*)(hb0 + m * WPAD + u2 * 2) = __floats2half2_rn(v.x, v.y);
    }
    __syncthreads();

    const int lane = tid & 31, warp = tid >> 5;
    const int n0 = warp * 32;
    const uint32_t wbase = (uint32_t)__cvta_generic_to_shared(Wsm);
    const uint32_t hoff = ((lane & 15) * WPAD + (lane >> 4) * 8) * 2;
    const uint32_t hs0 = (uint32_t)__cvta_generic_to_shared(hb0);
    const uint32_t hs1 = (uint32_t)__cvta_generic_to_shared(hb1);
    const int r = lane >> 2;

    // B fragments resident in registers: 16 ks x 2 p x 4 = 128 regs
    uint32_t Br[16][2][4];
#pragma unroll
    for (int ks = 0; ks < 16; ++ks)
#pragma unroll
        for (int p = 0; p < 2; ++p)
            ldsm4(Br[ks][p][0], Br[ks][p][1], Br[ks][p][2], Br[ks][p][3],
                  wbase + ((n0 + p * 16 + (lane & 15)) * WPAD + ks * 16 +
                           (lane >> 4) * 8) * 2);

    for (int t = 0; t < T_; ++t) {
        __half2 x0v[4][2];
#pragma unroll
        for (int j = 0; j < 4; ++j) {
            int col = n0 + j * 8 + (lane & 3) * 2;
            size_t base = ((size_t)t * BS_ + m0 + r) * U_ + col;
            x0v[j][0] = *(const __half2*)(g_X0 + base);
            x0v[j][1] = *(const __half2*)(g_X0 + base + 8 * U_);
        }
        uint32_t ha = ((t & 1) ? hs1 : hs0) + hoff;
        float acc[4][4] = {};
#pragma unroll
        for (int ks = 0; ks < 16; ++ks) {
            uint32_t a0, a1, a2, a3;
            ldsm4(a0, a1, a2, a3, ha + ks * 32);
            mma16816(acc[0], a0, a1, a2, a3, Br[ks][0][0], Br[ks][0][2]);
            mma16816(acc[1], a0, a1, a2, a3, Br[ks][0][1], Br[ks][0][3]);
            mma16816(acc[2], a0, a1, a2, a3, Br[ks][1][0], Br[ks][1][2]);
            mma16816(acc[3], a0, a1, a2, a3, Br[ks][1][1], Br[ks][1][3]);
        }
        __half* hn = (t & 1) ? hb0 : hb1;
#pragma unroll
        for (int j = 0; j < 4; ++j) {
            int col = n0 + j * 8 + (lane & 3) * 2;
            float2 xa = __half22float2(x0v[j][0]);
            float2 xb = __half22float2(x0v[j][1]);
            __half2 p0 = __floats2half2_rn(ftanh(acc[j][0] + xa.x), ftanh(acc[j][1] + xa.y));
            __half2 p1 = __floats2half2_rn(ftanh(acc[j][2] + xb.x), ftanh(acc[j][3] + xb.y));
            *(__half2*)(hn + r * WPAD + col) = p0;
            *(__half2*)(hn + (r + 8) * WPAD + col) = p1;
            size_t base = ((size_t)t * BS_ + m0 + r) * U_ + col;
            *(__half2*)(g_H0 + base) = p0;
            *(__half2*)(g_H0 + base + 8 * U_) = p1;
        }
        __syncthreads();
    }
}

// ---------------- K3: Z1 = H0 @ Wx1 + b1 -- proper 128-row-tile GEMM ----------------
// grid 640 x 256 thr; CTA: B resident, 2 tiles of M=128 (full N=256, K=256).
__global__ __launch_bounds__(256, 1) void k_z1b(const float* __restrict__ bias) {
    extern __shared__ __half sm[];
    __half* Wsm = sm;               // 256 x 264
    __half* Asm = sm + U_ * WPAD;   // 128 x 264
    const int tid = threadIdx.x;
    const int lane = tid & 31, warp = tid >> 5;
    const int wm0 = (warp & 3) * 32;        // 4 m-warps
    const int wn0 = (warp >> 2) * 128;      // 2 n-warps
    for (int i8 = tid; i8 < U_ * U_ / 8; i8 += 256) {
        int rr = i8 >> 5, c8 = i8 & 31;
        *(uint4*)(Wsm + rr * WPAD + c8 * 8) = *(const uint4*)(g_WT1 + rr * U_ + c8 * 8);
    }
    const uint32_t wbase = (uint32_t)__cvta_generic_to_shared(Wsm);
    const uint32_t abase = (uint32_t)__cvta_generic_to_shared(Asm);
    const int r = lane >> 2;

    for (int tile = 0; tile < 2; ++tile) {
        const int gm = blockIdx.x * 256 + tile * 128;
        __syncthreads();
        for (int i8 = tid; i8 < 128 * 32; i8 += 256) {
            int m = i8 >> 5, c8 = i8 & 31;
            *(uint4*)(Asm + m * WPAD + c8 * 8) =
                *(const uint4*)(g_H0 + (size_t)(gm + m) * U_ + c8 * 8);
        }
        __syncthreads();

        float acc[2][16][4];
#pragma unroll
        for (int mf = 0; mf < 2; ++mf)
#pragma unroll
            for (int j = 0; j < 16; ++j)
#pragma unroll
                for (int q = 0; q < 4; ++q) acc[mf][j][q] = 0.0f;

#pragma unroll
        for (int ks = 0; ks < 16; ++ks) {
            uint32_t a[2][4];
#pragma unroll
            for (int mf = 0; mf < 2; ++mf)
                ldsm4(a[mf][0], a[mf][1], a[mf][2], a[mf][3],
                      abase + ((wm0 + mf * 16 + (lane & 15)) * WPAD + ks * 16 +
                               (lane >> 4) * 8) * 2);
#pragma unroll
            for (int jn = 0; jn < 8; ++jn) {
                uint32_t b0, b1, b2, b3;
                ldsm4(b0, b1, b2, b3,
                      wbase + ((wn0 + jn * 16 + (lane & 15)) * WPAD + ks * 16 +
                               (lane >> 4) * 8) * 2);
                mma16816(acc[0][2 * jn],     a[0][0], a[0][1], a[0][2], a[0][3], b0, b2);
                mma16816(acc[0][2 * jn + 1], a[0][0], a[0][1], a[0][2], a[0][3], b1, b3);
                mma16816(acc[1][2 * jn],     a[1][0], a[1][1], a[1][2], a[1][3], b0, b2);
                mma16816(acc[1][2 * jn + 1], a[1][0], a[1][1], a[1][2], a[1][3], b1, b3);
            }
        }
#pragma unroll
        for (int mf = 0; mf < 2; ++mf)
#pragma unroll
            for (int j = 0; j < 16; ++j) {
                int col = wn0 + j * 8 + (lane & 3) * 2;
                float bi0 = __ldg(bias + U_ + col), bi1 = __ldg(bias + U_ + col + 1);
                size_t row = (size_t)(gm + wm0 + mf * 16 + r);
                *(float2*)(g_Z1 + row * U_ + col) =
                    make_float2(acc[mf][j][0] + bi0, acc[mf][j][1] + bi1);
                *(float2*)(g_Z1 + (row + 8) * U_ + col) =
                    make_float2(acc[mf][j][2] + bi0, acc[mf][j][3] + bi1);
            }
    }
}

// ---------------- K4: layer-1 recurrence + fused head (B in registers) ----------------
__global__ __launch_bounds__(256, 1) void k_r1(const float* __restrict__ h0in,
                                               const float* __restrict__ Wo,
                                               const float* __restrict__ bo,
                                               float* __restrict__ out) {
    extern __shared__ __half sm[];
    __half* Wsm = sm;
    __half* hb0 = sm + U_ * WPAD;
    __half* hb1 = hb0 + 16 * WPAD;
    __shared__ float zs[16];
    const int tid = threadIdx.x;
    const int m0 = blockIdx.x * 16;
    if (tid < 16) zs[tid] = 0.0f;
    for (int i8 = tid; i8 < U_ * U_ / 8; i8 += 256) {
        int rr = i8 >> 5, c8 = i8 & 31;
        *(uint4*)(Wsm + rr * WPAD + c8 * 8) = *(const uint4*)(g_WT2 + rr * U_ + c8 * 8);
    }
    for (int i2 = tid; i2 < 16 * U_ / 2; i2 += 256) {
        int m = i2 >> 7, u2 = i2 & 127;
        float2 v = *(const float2*)(h0in + (size_t)BS_ * U_ + (size_t)(m0 + m) * U_ + u2 * 2);
        *(__half2*)(hb0 + m * WPAD + u2 * 2) = __floats2half2_rn(v.x, v.y);
    }
    __syncthreads();

    const int lane = tid & 31, warp = tid >> 5;
    const int n0 = warp * 32;
    const uint32_t wbase = (uint32_t)__cvta_generic_to_shared(Wsm);
    const uint32_t hoff = ((lane & 15) * WPAD + (lane >> 4) * 8) * 2;
    const uint32_t hs0 = (uint32_t)__cvta_generic_to_shared(hb0);
    const uint32_t hs1 = (uint32_t)__cvta_generic_to_shared(hb1);
    const int r = lane >> 2;

    uint32_t Br[16][2][4];
#pragma unroll
    for (int ks = 0; ks < 16; ++ks)
#pragma unroll
        for (int p = 0; p < 2; ++p)
            ldsm4(Br[ks][p][0], Br[ks][p][1], Br[ks][p][2], Br[ks][p][3],
                  wbase + ((n0 + p * 16 + (lane & 15)) * WPAD + ks * 16 +
                           (lane >> 4) * 8) * 2);

    for (int t = 0; t < T_; ++t) {
        float2 zv[4][2];
#pragma unroll
        for (int j = 0; j < 4; ++j) {
            int col = n0 + j * 8 + (lane & 3) * 2;
            size_t base = ((size_t)t * BS_ + m0 + r) * U_ + col;
            zv[j][0] = *(const float2*)(g_Z1 + base);
            zv[j][1] = *(const float2*)(g_Z1 + base + 8 * U_);
        }
        uint32_t ha = ((t & 1) ? hs1 : hs0) + hoff;
        float acc[4][4] = {};
#pragma unroll
        for (int ks = 0; ks < 16; ++ks) {
            uint32_t a0, a1, a2, a3;
            ldsm4(a0, a1, a2, a3, ha + ks * 32);
            mma16816(acc[0], a0, a1, a2, a3, Br[ks][0][0], Br[ks][0][2]);
            mma16816(acc[1], a0, a1, a2, a3, Br[ks][0][1], Br[ks][0][3]);
            mma16816(acc[2], a0, a1, a2, a3, Br[ks][1][0], Br[ks][1][2]);
            mma16816(acc[3], a0, a1, a2, a3, Br[ks][1][1], Br[ks][1][3]);
        }
        __half* hn = (t & 1) ? hb0 : hb1;
#pragma unroll
        for (int j = 0; j < 4; ++j) {
            int col = n0 + j * 8 + (lane & 3) * 2;
            float v0 = ftanh(acc[j][0] + zv[j][0].x);
            float v1 = ftanh(acc[j][1] + zv[j][0].y);
            float v2 = ftanh(acc[j][2] + zv[j][1].x);
            float v3 = ftanh(acc[j][3] + zv[j][1].y);
            *(__half2*)(hn + r * WPAD + col) = __floats2half2_rn(v0, v1);
            *(__half2*)(hn + (r + 8) * WPAD + col) = __floats2half2_rn(v2, v3);
            if (t == T_ - 1) {
                float w0 = __ldg(Wo + col), w1 = __ldg(Wo + col + 1);
                atomicAdd(&zs[r],     v0 * w0 + v1 * w1);
                atomicAdd(&zs[r + 8], v2 * w0 + v3 * w1);
            }
        }
        __syncthreads();
    }
    if (tid < 16) {
        float z = zs[tid] + bo[0];
        out[m0 + tid] = 1.0f / (1.0f + expf(-z));
    }
}

// ---------------- launcher ----------------
extern "C" void kernel_launch(void* const* d_in, const int* in_sizes, int n_in,
                              void* d_out, int out_size) {
    const int*   tokens = (const int*)  d_in[0];
    const float* emb    = (const float*)d_in[1];
    const float* Wx0    = (const float*)d_in[2];
    const float* Wx1    = (const float*)d_in[3];
    const float* Wh     = (const float*)d_in[4];
    const float* b      = (const float*)d_in[5];
    const float* h0     = (const float*)d_in[6];
    const float* Wo     = (const float*)d_in[7];
    const float* bo     = (const float*)d_in[8];
    float* out = (float*)d_out;

    const int smem_x0 = (256 * EPS_ + 16 * EPS_) * 2;
    const int smem_r  = (U_ * WPAD + 32 * WPAD) * 2;
    const int smem_z  = (U_ * WPAD + 128 * WPAD) * 2;   // 202752
    cudaFuncSetAttribute(k_x0, cudaFuncAttributeMaxDynamicSharedMemorySize, smem_x0);
    cudaFuncSetAttribute(k_r0, cudaFuncAttributeMaxDynamicSharedMemorySize, smem_r);
    cudaFuncSetAttribute(k_z1b, cudaFuncAttributeMaxDynamicSharedMemorySize, smem_z);
    cudaFuncSetAttribute(k_r1, cudaFuncAttributeMaxDynamicSharedMemorySize, smem_r);

    k_prep<<<(V_ * EP_ + 255) / 256, 256>>>(emb, Wx0, Wx1, Wh);
    dim3 g1(128, 8);
    k_x0<<<g1, 256, smem_x0>>>(tokens, b);
    k_r0<<<128, 256, smem_r>>>(h0);
    k_z1b<<<640, 256, smem_z>>>(b);
    k_r1<<<128, 256, smem_r>>>(h0, Wo, bo, out);
}

// round 5
// speedup vs baseline: 1.6699x; 1.1313x over previous
#include <cuda_runtime.h>
#include <cuda_fp16.h>
#include <math.h>
#include <stdint.h>

// dims: tokens [2048,80] i32, emb [10000,100] f32, Wx0 [100,256], Wx1 [256,256],
// Wh [2,256,256], b [2,256], h0 [2,2048,256], Wo [256,1], bo [1] -> out [2048,1] f32

#define T_ 80
#define BS_ 2048
#define U_ 256
#define E_ 100
#define EP_ 112
#define V_ 10000

#define WPAD 264      // smem k-stride for 256-wide (conflict-free ldmatrix)
#define EPS_ 120      // smem k-stride for 112-wide

// ---------------- scratch ----------------
__device__ __half g_emb16[V_ * EP_];
__device__ __half g_Wx0T[U_ * EP_];
__device__ __half g_WT0[U_ * U_];              // Wh0^T [n][k]
__device__ __half g_WT1[U_ * U_];              // Wx1^T [n][k]
__device__ __half g_WT2[U_ * U_];              // Wh1^T [n][k]
__device__ __half g_X0[(size_t)T_ * BS_ * U_];  // x@Wx0+b0 (fp16)
__device__ __half g_Z1h[(size_t)T_ * BS_ * U_]; // h0@Wx1+b1 (fp16)

// ---------------- helpers ----------------
__device__ __forceinline__ void ldsm4(uint32_t &r0, uint32_t &r1, uint32_t &r2,
                                      uint32_t &r3, uint32_t addr) {
    asm volatile("ldmatrix.sync.aligned.m8n8.x4.shared.b16 {%0,%1,%2,%3}, [%4];\n"
                 : "=r"(r0), "=r"(r1), "=r"(r2), "=r"(r3) : "r"(addr));
}

__device__ __forceinline__ void mma16816(float c[4], uint32_t a0, uint32_t a1,
                                         uint32_t a2, uint32_t a3,
                                         uint32_t b0, uint32_t b1) {
    asm volatile(
        "mma.sync.aligned.m16n8k16.row.col.f32.f16.f16.f32 "
        "{%0,%1,%2,%3},{%4,%5,%6,%7},{%8,%9},{%0,%1,%2,%3};\n"
        : "+f"(c[0]), "+f"(c[1]), "+f"(c[2]), "+f"(c[3])
        : "r"(a0), "r"(a1), "r"(a2), "r"(a3), "r"(b0), "r"(b1));
}

__device__ __forceinline__ float ftanh(float x) {
    float e = __expf(-2.0f * fabsf(x));
    float r = __fdividef(1.0f - e, 1.0f + e);
    return copysignf(r, x);
}

// ---------------- K0: prep ----------------
__global__ void k_prep(const float* __restrict__ emb, const float* __restrict__ Wx0,
                       const float* __restrict__ Wx1, const float* __restrict__ Wh) {
    int i = blockIdx.x * 256 + threadIdx.x;
    if (i < V_ * EP_) {
        int v = i / EP_, e = i - v * EP_;
        g_emb16[i] = __float2half(e < E_ ? emb[v * E_ + e] : 0.0f);
    }
    if (i < U_ * U_) {
        int n = i >> 8, k = i & 255;
        g_WT0[i] = __float2half(Wh[k * U_ + n]);
        g_WT1[i] = __float2half(Wx1[k * U_ + n]);
        g_WT2[i] = __float2half(Wh[U_ * U_ + k * U_ + n]);
    }
    if (i < U_ * EP_) {
        int u = i / EP_, e = i - u * EP_;
        g_Wx0T[i] = __float2half(e < E_ ? Wx0[e * U_ + u] : 0.0f);
    }
}

// ---------------- K1: X0 = emb[tok] @ Wx0 + b0 ----------------
__global__ __launch_bounds__(256, 1) void k_x0(const int* __restrict__ tokens,
                                               const float* __restrict__ bias) {
    extern __shared__ __half sm[];
    __half* Wsm = sm;               // 256 x 120
    __half* Asm = sm + 256 * EPS_;  // 16 x 120
    const int tid = threadIdx.x;
    const int m0 = blockIdx.x * 16;
    for (int i8 = tid; i8 < U_ * EP_ / 8; i8 += 256) {
        int r = i8 / 14, c8 = i8 - r * 14;
        *(uint4*)(Wsm + r * EPS_ + c8 * 8) = *(const uint4*)(g_Wx0T + r * EP_ + c8 * 8);
    }
    __syncthreads();
    const int lane = tid & 31, warp = tid >> 5;
    const int n0 = warp * 32;
    const uint32_t a_off = (uint32_t)__cvta_generic_to_shared(Asm) +
                           ((lane & 15) * EPS_ + (lane >> 4) * 8) * 2;
    const uint32_t wbase = (uint32_t)__cvta_generic_to_shared(Wsm);
    const int r = lane >> 2;

    uint32_t Br[7][2][4];
#pragma unroll
    for (int ks = 0; ks < 7; ++ks)
#pragma unroll
        for (int p = 0; p < 2; ++p)
            ldsm4(Br[ks][p][0], Br[ks][p][1], Br[ks][p][2], Br[ks][p][3],
                  wbase + ((n0 + p * 16 + (lane & 15)) * EPS_ + ks * 16 +
                           (lane >> 4) * 8) * 2);

    for (int tt = 0; tt < 10; ++tt) {
        int t = blockIdx.y * 10 + tt;
        __syncthreads();
        if (tid < 224) {
            int m = tid / 14, c8 = tid - m * 14;
            int tok = tokens[(m0 + m) * T_ + t];
            *(uint4*)(Asm + m * EPS_ + c8 * 8) =
                *(const uint4*)(g_emb16 + (size_t)tok * EP_ + c8 * 8);
        }
        __syncthreads();
        float acc[4][4] = {};
#pragma unroll
        for (int ks = 0; ks < 7; ++ks) {
            uint32_t a0, a1, a2, a3;
            ldsm4(a0, a1, a2, a3, a_off + ks * 32);
            mma16816(acc[0], a0, a1, a2, a3, Br[ks][0][0], Br[ks][0][2]);
            mma16816(acc[1], a0, a1, a2, a3, Br[ks][0][1], Br[ks][0][3]);
            mma16816(acc[2], a0, a1, a2, a3, Br[ks][1][0], Br[ks][1][2]);
            mma16816(acc[3], a0, a1, a2, a3, Br[ks][1][1], Br[ks][1][3]);
        }
#pragma unroll
        for (int j = 0; j < 4; ++j) {
            int col = n0 + j * 8 + (lane & 3) * 2;
            float bi0 = bias[col], bi1 = bias[col + 1];
            size_t base = ((size_t)t * BS_ + m0 + r) * U_ + col;
            *(__half2*)(g_X0 + base) = __floats2half2_rn(acc[j][0] + bi0, acc[j][1] + bi1);
            *(__half2*)(g_X0 + base + 8 * U_) = __floats2half2_rn(acc[j][2] + bi0, acc[j][3] + bi1);
        }
    }
}

// ---------------- K2: fused layer-0 recurrence + Wx1 GEMM ----------------
// per step: h = tanh(X0[t] + h@Wh0) [B0 in regs]; Z1[t] = h@Wx1 + b1 [B1 in smem] -> fp16 gmem
__global__ __launch_bounds__(256, 1) void k_r0f(const float* __restrict__ h0in,
                                                const float* __restrict__ bias) {
    extern __shared__ __half sm[];
    __half* Wsm = sm;                   // 256 x 264 : stage Wh0T first, then Wx1T
    __half* hb0 = sm + U_ * WPAD;       // 16 x 264 double buffer
    __half* hb1 = hb0 + 16 * WPAD;
    const int tid = threadIdx.x;
    const int m0 = blockIdx.x * 16;
    const int lane = tid & 31, warp = tid >> 5;
    const int n0 = warp * 32;
    const uint32_t wbase = (uint32_t)__cvta_generic_to_shared(Wsm);
    const uint32_t hoff = ((lane & 15) * WPAD + (lane >> 4) * 8) * 2;
    const uint32_t hs0 = (uint32_t)__cvta_generic_to_shared(hb0);
    const uint32_t hs1 = (uint32_t)__cvta_generic_to_shared(hb1);
    const int r = lane >> 2;

    // stage Wh0T, init h state
    for (int i8 = tid; i8 < U_ * U_ / 8; i8 += 256) {
        int rr = i8 >> 5, c8 = i8 & 31;
        *(uint4*)(Wsm + rr * WPAD + c8 * 8) = *(const uint4*)(g_WT0 + rr * U_ + c8 * 8);
    }
    for (int i2 = tid; i2 < 16 * U_ / 2; i2 += 256) {
        int m = i2 >> 7, u2 = i2 & 127;
        float2 v = *(const float2*)(h0in + (size_t)(m0 + m) * U_ + u2 * 2);
        *(__half2*)(hb0 + m * WPAD + u2 * 2) = __floats2half2_rn(v.x, v.y);
    }
    __syncthreads();

    // B0 (Wh0T) fragments -> registers
    uint32_t B0r[16][2][4];
#pragma unroll
    for (int ks = 0; ks < 16; ++ks)
#pragma unroll
        for (int p = 0; p < 2; ++p)
            ldsm4(B0r[ks][p][0], B0r[ks][p][1], B0r[ks][p][2], B0r[ks][p][3],
                  wbase + ((n0 + p * 16 + (lane & 15)) * WPAD + ks * 16 +
                           (lane >> 4) * 8) * 2);
    __syncthreads();
    // overwrite staging with Wx1T (B1, read from smem each step)
    for (int i8 = tid; i8 < U_ * U_ / 8; i8 += 256) {
        int rr = i8 >> 5, c8 = i8 & 31;
        *(uint4*)(Wsm + rr * WPAD + c8 * 8) = *(const uint4*)(g_WT1 + rr * U_ + c8 * 8);
    }
    // b1 per-thread
    float2 b1v[4];
#pragma unroll
    for (int j = 0; j < 4; ++j) {
        int col = n0 + j * 8 + (lane & 3) * 2;
        b1v[j] = make_float2(__ldg(bias + U_ + col), __ldg(bias + U_ + col + 1));
    }
    __syncthreads();

    for (int t = 0; t < T_; ++t) {
        // prefetch X0[t]
        __half2 x0v[4][2];
#pragma unroll
        for (int j = 0; j < 4; ++j) {
            int col = n0 + j * 8 + (lane & 3) * 2;
            size_t base = ((size_t)t * BS_ + m0 + r) * U_ + col;
            x0v[j][0] = *(const __half2*)(g_X0 + base);
            x0v[j][1] = *(const __half2*)(g_X0 + base + 8 * U_);
        }
        const uint32_t hcur = ((t & 1) ? hs1 : hs0) + hoff;
        const uint32_t hnxts = (t & 1) ? hs0 : hs1;
        __half* hn = (t & 1) ? hb0 : hb1;

        // GEMM1: h @ Wh0 (B in regs)
        float acc[4][4] = {};
#pragma unroll
        for (int ks = 0; ks < 16; ++ks) {
            uint32_t a0, a1, a2, a3;
            ldsm4(a0, a1, a2, a3, hcur + ks * 32);
            mma16816(acc[0], a0, a1, a2, a3, B0r[ks][0][0], B0r[ks][0][2]);
            mma16816(acc[1], a0, a1, a2, a3, B0r[ks][0][1], B0r[ks][0][3]);
            mma16816(acc[2], a0, a1, a2, a3, B0r[ks][1][0], B0r[ks][1][2]);
            mma16816(acc[3], a0, a1, a2, a3, B0r[ks][1][1], B0r[ks][1][3]);
        }
        // epi: tanh -> new h into other buffer
#pragma unroll
        for (int j = 0; j < 4; ++j) {
            int col = n0 + j * 8 + (lane & 3) * 2;
            float2 xa = __half22float2(x0v[j][0]);
            float2 xb = __half22float2(x0v[j][1]);
            *(__half2*)(hn + r * WPAD + col) =
                __floats2half2_rn(ftanh(acc[j][0] + xa.x), ftanh(acc[j][1] + xa.y));
            *(__half2*)(hn + (r + 8) * WPAD + col) =
                __floats2half2_rn(ftanh(acc[j][2] + xb.x), ftanh(acc[j][3] + xb.y));
        }
        __syncthreads();

        // GEMM2: hnew @ Wx1 + b1 -> Z1[t] (fp16 gmem)
        float zac[4][4] = {};
        const uint32_t ha2 = hnxts + hoff;
#pragma unroll
        for (int ks = 0; ks < 16; ++ks) {
            uint32_t a0, a1, a2, a3;
            ldsm4(a0, a1, a2, a3, ha2 + ks * 32);
            uint32_t b0, b1_, b2, b3;
            ldsm4(b0, b1_, b2, b3,
                  wbase + ((n0 + (lane & 15)) * WPAD + ks * 16 + (lane >> 4) * 8) * 2);
            mma16816(zac[0], a0, a1, a2, a3, b0, b2);
            mma16816(zac[1], a0, a1, a2, a3, b1_, b3);
            ldsm4(b0, b1_, b2, b3,
                  wbase + ((n0 + 16 + (lane & 15)) * WPAD + ks * 16 + (lane >> 4) * 8) * 2);
            mma16816(zac[2], a0, a1, a2, a3, b0, b2);
            mma16816(zac[3], a0, a1, a2, a3, b1_, b3);
        }
#pragma unroll
        for (int j = 0; j < 4; ++j) {
            int col = n0 + j * 8 + (lane & 3) * 2;
            size_t base = ((size_t)t * BS_ + m0 + r) * U_ + col;
            *(__half2*)(g_Z1h + base) =
                __floats2half2_rn(zac[j][0] + b1v[j].x, zac[j][1] + b1v[j].y);
            *(__half2*)(g_Z1h + base + 8 * U_) =
                __floats2half2_rn(zac[j][2] + b1v[j].x, zac[j][3] + b1v[j].y);
        }
        // no extra barrier needed: next GEMM1 reads the buffer written before
        // this step's barrier; the other buffer is only overwritten after the
        // next barrier-free region's reads are from disjoint memory.
    }
}

// ---------------- K3: layer-1 recurrence + fused head (B in registers) ----------------
__global__ __launch_bounds__(256, 1) void k_r1(const float* __restrict__ h0in,
                                               const float* __restrict__ Wo,
                                               const float* __restrict__ bo,
                                               float* __restrict__ out) {
    extern __shared__ __half sm[];
    __half* Wsm = sm;
    __half* hb0 = sm + U_ * WPAD;
    __half* hb1 = hb0 + 16 * WPAD;
    __shared__ float zs[16];
    const int tid = threadIdx.x;
    const int m0 = blockIdx.x * 16;
    if (tid < 16) zs[tid] = 0.0f;
    for (int i8 = tid; i8 < U_ * U_ / 8; i8 += 256) {
        int rr = i8 >> 5, c8 = i8 & 31;
        *(uint4*)(Wsm + rr * WPAD + c8 * 8) = *(const uint4*)(g_WT2 + rr * U_ + c8 * 8);
    }
    for (int i2 = tid; i2 < 16 * U_ / 2; i2 += 256) {
        int m = i2 >> 7, u2 = i2 & 127;
        float2 v = *(const float2*)(h0in + (size_t)BS_ * U_ + (size_t)(m0 + m) * U_ + u2 * 2);
        *(__half2*)(hb0 + m * WPAD + u2 * 2) = __floats2half2_rn(v.x, v.y);
    }
    __syncthreads();

    const int lane = tid & 31, warp = tid >> 5;
    const int n0 = warp * 32;
    const uint32_t wbase = (uint32_t)__cvta_generic_to_shared(Wsm);
    const uint32_t hoff = ((lane & 15) * WPAD + (lane >> 4) * 8) * 2;
    const uint32_t hs0 = (uint32_t)__cvta_generic_to_shared(hb0);
    const uint32_t hs1 = (uint32_t)__cvta_generic_to_shared(hb1);
    const int r = lane >> 2;

    uint32_t Br[16][2][4];
#pragma unroll
    for (int ks = 0; ks < 16; ++ks)
#pragma unroll
        for (int p = 0; p < 2; ++p)
            ldsm4(Br[ks][p][0], Br[ks][p][1], Br[ks][p][2], Br[ks][p][3],
                  wbase + ((n0 + p * 16 + (lane & 15)) * WPAD + ks * 16 +
                           (lane >> 4) * 8) * 2);

    for (int t = 0; t < T_; ++t) {
        __half2 zv[4][2];
#pragma unroll
        for (int j = 0; j < 4; ++j) {
            int col = n0 + j * 8 + (lane & 3) * 2;
            size_t base = ((size_t)t * BS_ + m0 + r) * U_ + col;
            zv[j][0] = *(const __half2*)(g_Z1h + base);
            zv[j][1] = *(const __half2*)(g_Z1h + base + 8 * U_);
        }
        uint32_t ha = ((t & 1) ? hs1 : hs0) + hoff;
        float acc[4][4] = {};
#pragma unroll
        for (int ks = 0; ks < 16; ++ks) {
            uint32_t a0, a1, a2, a3;
            ldsm4(a0, a1, a2, a3, ha + ks * 32);
            mma16816(acc[0], a0, a1, a2, a3, Br[ks][0][0], Br[ks][0][2]);
            mma16816(acc[1], a0, a1, a2, a3, Br[ks][0][1], Br[ks][0][3]);
            mma16816(acc[2], a0, a1, a2, a3, Br[ks][1][0], Br[ks][1][2]);
            mma16816(acc[3], a0, a1, a2, a3, Br[ks][1][1], Br[ks][1][3]);
        }
        __half* hn = (t & 1) ? hb0 : hb1;
#pragma unroll
        for (int j = 0; j < 4; ++j) {
            int col = n0 + j * 8 + (lane & 3) * 2;
            float2 za = __half22float2(zv[j][0]);
            float2 zb = __half22float2(zv[j][1]);
            float v0 = ftanh(acc[j][0] + za.x);
            float v1 = ftanh(acc[j][1] + za.y);
            float v2 = ftanh(acc[j][2] + zb.x);
            float v3 = ftanh(acc[j][3] + zb.y);
            *(__half2*)(hn + r * WPAD + col) = __floats2half2_rn(v0, v1);
            *(__half2*)(hn + (r + 8) * WPAD + col) = __floats2half2_rn(v2, v3);
            if (t == T_ - 1) {
                float w0 = __ldg(Wo + col), w1 = __ldg(Wo + col + 1);
                atomicAdd(&zs[r],     v0 * w0 + v1 * w1);
                atomicAdd(&zs[r + 8], v2 * w0 + v3 * w1);
            }
        }
        __syncthreads();
    }
    if (tid < 16) {
        float z = zs[tid] + bo[0];
        out[m0 + tid] = 1.0f / (1.0f + expf(-z));
    }
}

// ---------------- launcher ----------------
extern "C" void kernel_launch(void* const* d_in, const int* in_sizes, int n_in,
                              void* d_out, int out_size) {
    const int*   tokens = (const int*)  d_in[0];
    const float* emb    = (const float*)d_in[1];
    const float* Wx0    = (const float*)d_in[2];
    const float* Wx1    = (const float*)d_in[3];
    const float* Wh     = (const float*)d_in[4];
    const float* b      = (const float*)d_in[5];
    const float* h0     = (const float*)d_in[6];
    const float* Wo     = (const float*)d_in[7];
    const float* bo     = (const float*)d_in[8];
    float* out = (float*)d_out;

    const int smem_x0 = (256 * EPS_ + 16 * EPS_) * 2;
    const int smem_r  = (U_ * WPAD + 32 * WPAD) * 2;   // 152064
    cudaFuncSetAttribute(k_x0,  cudaFuncAttributeMaxDynamicSharedMemorySize, smem_x0);
    cudaFuncSetAttribute(k_r0f, cudaFuncAttributeMaxDynamicSharedMemorySize, smem_r);
    cudaFuncSetAttribute(k_r1,  cudaFuncAttributeMaxDynamicSharedMemorySize, smem_r);

    k_prep<<<(V_ * EP_ + 255) / 256, 256>>>(emb, Wx0, Wx1, Wh);
    dim3 g1(128, 8);
    k_x0<<<g1, 256, smem_x0>>>(tokens, b);
    k_r0f<<<128, 256, smem_r>>>(h0, b);
    k_r1<<<128, 256, smem_r>>>(h0, Wo, bo, out);
}

// round 6
// speedup vs baseline: 1.7152x; 1.0271x over previous
#include <cuda_runtime.h>
#include <cuda_fp16.h>
#include <math.h>
#include <stdint.h>

// dims: tokens [2048,80] i32, emb [10000,100] f32, Wx0 [100,256], Wx1 [256,256],
// Wh [2,256,256], b [2,256], h0 [2,2048,256], Wo [256,1], bo [1] -> out [2048,1] f32

#define T_ 80
#define BS_ 2048
#define U_ 256
#define E_ 100
#define EP_ 112
#define V_ 10000

#define WPAD 264      // smem k-stride for 256-wide (conflict-free ldmatrix)
#define EPS_ 120      // smem k-stride for 112-wide

// ---------------- scratch ----------------
__device__ __half g_emb16[V_ * EP_];
__device__ __half g_Wx0T[U_ * EP_];
__device__ __half g_WT0[U_ * U_];              // Wh0^T [n][k]
__device__ __half g_WT1[U_ * U_];              // Wx1^T [n][k]
__device__ __half g_WT2[U_ * U_];              // Wh1^T [n][k]
__device__ __half g_X0[(size_t)T_ * BS_ * U_];  // x@Wx0+b0 (fp16)
__device__ __half g_Z1h[(size_t)T_ * BS_ * U_]; // h0@Wx1+b1 (fp16)

// ---------------- helpers ----------------
__device__ __forceinline__ void ldsm4(uint32_t &r0, uint32_t &r1, uint32_t &r2,
                                      uint32_t &r3, uint32_t addr) {
    asm volatile("ldmatrix.sync.aligned.m8n8.x4.shared.b16 {%0,%1,%2,%3}, [%4];\n"
                 : "=r"(r0), "=r"(r1), "=r"(r2), "=r"(r3) : "r"(addr));
}

__device__ __forceinline__ void mma16816(float c[4], uint32_t a0, uint32_t a1,
                                         uint32_t a2, uint32_t a3,
                                         uint32_t b0, uint32_t b1) {
    asm volatile(
        "mma.sync.aligned.m16n8k16.row.col.f32.f16.f16.f32 "
        "{%0,%1,%2,%3},{%4,%5,%6,%7},{%8,%9},{%0,%1,%2,%3};\n"
        : "+f"(c[0]), "+f"(c[1]), "+f"(c[2]), "+f"(c[3])
        : "r"(a0), "r"(a1), "r"(a2), "r"(a3), "r"(b0), "r"(b1));
}

__device__ __forceinline__ float ftanh(float x) {
    float y;
    asm("tanh.approx.f32 %0, %1;" : "=f"(y) : "f"(x));
    return y;
}

// ---------------- K0: prep ----------------
__global__ void k_prep(const float* __restrict__ emb, const float* __restrict__ Wx0,
                       const float* __restrict__ Wx1, const float* __restrict__ Wh) {
    int i = blockIdx.x * 256 + threadIdx.x;
    if (i < V_ * EP_) {
        int v = i / EP_, e = i - v * EP_;
        g_emb16[i] = __float2half(e < E_ ? emb[v * E_ + e] : 0.0f);
    }
    if (i < U_ * U_) {
        int n = i >> 8, k = i & 255;
        g_WT0[i] = __float2half(Wh[k * U_ + n]);
        g_WT1[i] = __float2half(Wx1[k * U_ + n]);
        g_WT2[i] = __float2half(Wh[U_ * U_ + k * U_ + n]);
    }
    if (i < U_ * EP_) {
        int u = i / EP_, e = i - u * EP_;
        g_Wx0T[i] = __float2half(e < E_ ? Wx0[e * U_ + u] : 0.0f);
    }
}

// ---------------- K1: X0 = emb[tok] @ Wx0 + b0 ----------------
__global__ __launch_bounds__(256, 1) void k_x0(const int* __restrict__ tokens,
                                               const float* __restrict__ bias) {
    extern __shared__ __half sm[];
    __half* Wsm = sm;               // 256 x 120
    __half* Asm = sm + 256 * EPS_;  // 16 x 120
    const int tid = threadIdx.x;
    const int m0 = blockIdx.x * 16;
    for (int i8 = tid; i8 < U_ * EP_ / 8; i8 += 256) {
        int r = i8 / 14, c8 = i8 - r * 14;
        *(uint4*)(Wsm + r * EPS_ + c8 * 8) = *(const uint4*)(g_Wx0T + r * EP_ + c8 * 8);
    }
    __syncthreads();
    const int lane = tid & 31, warp = tid >> 5;
    const int n0 = warp * 32;
    const uint32_t a_off = (uint32_t)__cvta_generic_to_shared(Asm) +
                           ((lane & 15) * EPS_ + (lane >> 4) * 8) * 2;
    const uint32_t wbase = (uint32_t)__cvta_generic_to_shared(Wsm);
    const int r = lane >> 2;

    uint32_t Br[7][2][4];
#pragma unroll
    for (int ks = 0; ks < 7; ++ks)
#pragma unroll
        for (int p = 0; p < 2; ++p)
            ldsm4(Br[ks][p][0], Br[ks][p][1], Br[ks][p][2], Br[ks][p][3],
                  wbase + ((n0 + p * 16 + (lane & 15)) * EPS_ + ks * 16 +
                           (lane >> 4) * 8) * 2);

    for (int tt = 0; tt < 10; ++tt) {
        int t = blockIdx.y * 10 + tt;
        __syncthreads();
        if (tid < 224) {
            int m = tid / 14, c8 = tid - m * 14;
            int tok = tokens[(m0 + m) * T_ + t];
            *(uint4*)(Asm + m * EPS_ + c8 * 8) =
                *(const uint4*)(g_emb16 + (size_t)tok * EP_ + c8 * 8);
        }
        __syncthreads();
        float acc[4][4] = {};
#pragma unroll
        for (int ks = 0; ks < 7; ++ks) {
            uint32_t a0, a1, a2, a3;
            ldsm4(a0, a1, a2, a3, a_off + ks * 32);
            mma16816(acc[0], a0, a1, a2, a3, Br[ks][0][0], Br[ks][0][2]);
            mma16816(acc[1], a0, a1, a2, a3, Br[ks][0][1], Br[ks][0][3]);
            mma16816(acc[2], a0, a1, a2, a3, Br[ks][1][0], Br[ks][1][2]);
            mma16816(acc[3], a0, a1, a2, a3, Br[ks][1][1], Br[ks][1][3]);
        }
#pragma unroll
        for (int j = 0; j < 4; ++j) {
            int col = n0 + j * 8 + (lane & 3) * 2;
            float bi0 = bias[col], bi1 = bias[col + 1];
            size_t base = ((size_t)t * BS_ + m0 + r) * U_ + col;
            *(__half2*)(g_X0 + base) = __floats2half2_rn(acc[j][0] + bi0, acc[j][1] + bi1);
            *(__half2*)(g_X0 + base + 8 * U_) = __floats2half2_rn(acc[j][2] + bi0, acc[j][3] + bi1);
        }
    }
}

// ---------------- K2: fused layer-0 recurrence + Wx1 GEMM (512 thr, 16 warps) ----------------
__global__ __launch_bounds__(512, 1) void k_r0f(const float* __restrict__ h0in,
                                                const float* __restrict__ bias) {
    extern __shared__ __half sm[];
    __half* Wsm = sm;                   // 256 x 264 : stage Wh0T first, then Wx1T
    __half* hb0 = sm + U_ * WPAD;       // 16 x 264 double buffer
    __half* hb1 = hb0 + 16 * WPAD;
    const int tid = threadIdx.x;
    const int m0 = blockIdx.x * 16;
    const int lane = tid & 31, warp = tid >> 5;
    const int n0 = warp * 16;           // 16-col slice per warp
    const uint32_t wbase = (uint32_t)__cvta_generic_to_shared(Wsm);
    const uint32_t hoff = ((lane & 15) * WPAD + (lane >> 4) * 8) * 2;
    const uint32_t hs0 = (uint32_t)__cvta_generic_to_shared(hb0);
    const uint32_t hs1 = (uint32_t)__cvta_generic_to_shared(hb1);
    const int r = lane >> 2;

    // stage Wh0T, init h state
    for (int i8 = tid; i8 < U_ * U_ / 8; i8 += 512) {
        int rr = i8 >> 5, c8 = i8 & 31;
        *(uint4*)(Wsm + rr * WPAD + c8 * 8) = *(const uint4*)(g_WT0 + rr * U_ + c8 * 8);
    }
    for (int i2 = tid; i2 < 16 * U_ / 2; i2 += 512) {
        int m = i2 >> 7, u2 = i2 & 127;
        float2 v = *(const float2*)(h0in + (size_t)(m0 + m) * U_ + u2 * 2);
        *(__half2*)(hb0 + m * WPAD + u2 * 2) = __floats2half2_rn(v.x, v.y);
    }
    __syncthreads();

    // B0 (Wh0T) fragments -> registers: 16 ks x 4 = 64 regs
    uint32_t B0r[16][4];
#pragma unroll
    for (int ks = 0; ks < 16; ++ks)
        ldsm4(B0r[ks][0], B0r[ks][1], B0r[ks][2], B0r[ks][3],
              wbase + ((n0 + (lane & 15)) * WPAD + ks * 16 + (lane >> 4) * 8) * 2);
    __syncthreads();
    // overwrite staging with Wx1T (B1, read from smem each step)
    for (int i8 = tid; i8 < U_ * U_ / 8; i8 += 512) {
        int rr = i8 >> 5, c8 = i8 & 31;
        *(uint4*)(Wsm + rr * WPAD + c8 * 8) = *(const uint4*)(g_WT1 + rr * U_ + c8 * 8);
    }
    float2 b1v[2];
#pragma unroll
    for (int j = 0; j < 2; ++j) {
        int col = n0 + j * 8 + (lane & 3) * 2;
        b1v[j] = make_float2(__ldg(bias + U_ + col), __ldg(bias + U_ + col + 1));
    }
    __syncthreads();

    for (int t = 0; t < T_; ++t) {
        // prefetch X0[t]
        __half2 x0v[2][2];
#pragma unroll
        for (int j = 0; j < 2; ++j) {
            int col = n0 + j * 8 + (lane & 3) * 2;
            size_t base = ((size_t)t * BS_ + m0 + r) * U_ + col;
            x0v[j][0] = *(const __half2*)(g_X0 + base);
            x0v[j][1] = *(const __half2*)(g_X0 + base + 8 * U_);
        }
        const uint32_t hcur = ((t & 1) ? hs1 : hs0) + hoff;
        const uint32_t hnxts = (t & 1) ? hs0 : hs1;
        __half* hn = (t & 1) ? hb0 : hb1;

        // GEMM1: h @ Wh0 (B in regs)
        float acc[2][4] = {};
#pragma unroll
        for (int ks = 0; ks < 16; ++ks) {
            uint32_t a0, a1, a2, a3;
            ldsm4(a0, a1, a2, a3, hcur + ks * 32);
            mma16816(acc[0], a0, a1, a2, a3, B0r[ks][0], B0r[ks][2]);
            mma16816(acc[1], a0, a1, a2, a3, B0r[ks][1], B0r[ks][3]);
        }
        // epi: tanh -> new h into other buffer
#pragma unroll
        for (int j = 0; j < 2; ++j) {
            int col = n0 + j * 8 + (lane & 3) * 2;
            float2 xa = __half22float2(x0v[j][0]);
            float2 xb = __half22float2(x0v[j][1]);
            *(__half2*)(hn + r * WPAD + col) =
                __floats2half2_rn(ftanh(acc[j][0] + xa.x), ftanh(acc[j][1] + xa.y));
            *(__half2*)(hn + (r + 8) * WPAD + col) =
                __floats2half2_rn(ftanh(acc[j][2] + xb.x), ftanh(acc[j][3] + xb.y));
        }
        __syncthreads();

        // GEMM2: hnew @ Wx1 + b1 -> Z1[t] (fp16 gmem)
        float zac[2][4] = {};
        const uint32_t ha2 = hnxts + hoff;
#pragma unroll
        for (int ks = 0; ks < 16; ++ks) {
            uint32_t a0, a1, a2, a3;
            ldsm4(a0, a1, a2, a3, ha2 + ks * 32);
            uint32_t b0, b1_, b2, b3;
            ldsm4(b0, b1_, b2, b3,
                  wbase + ((n0 + (lane & 15)) * WPAD + ks * 16 + (lane >> 4) * 8) * 2);
            mma16816(zac[0], a0, a1, a2, a3, b0, b2);
            mma16816(zac[1], a0, a1, a2, a3, b1_, b3);
        }
#pragma unroll
        for (int j = 0; j < 2; ++j) {
            int col = n0 + j * 8 + (lane & 3) * 2;
            size_t base = ((size_t)t * BS_ + m0 + r) * U_ + col;
            *(__half2*)(g_Z1h + base) =
                __floats2half2_rn(zac[j][0] + b1v[j].x, zac[j][1] + b1v[j].y);
            *(__half2*)(g_Z1h + base + 8 * U_) =
                __floats2half2_rn(zac[j][2] + b1v[j].x, zac[j][3] + b1v[j].y);
        }
    }
}

// ---------------- K3: layer-1 recurrence + fused head (512 thr, 16 warps) ----------------
__global__ __launch_bounds__(512, 1) void k_r1(const float* __restrict__ h0in,
                                               const float* __restrict__ Wo,
                                               const float* __restrict__ bo,
                                               float* __restrict__ out) {
    extern __shared__ __half sm[];
    __half* Wsm = sm;
    __half* hb0 = sm + U_ * WPAD;
    __half* hb1 = hb0 + 16 * WPAD;
    __shared__ float zs[16];
    const int tid = threadIdx.x;
    const int m0 = blockIdx.x * 16;
    if (tid < 16) zs[tid] = 0.0f;
    for (int i8 = tid; i8 < U_ * U_ / 8; i8 += 512) {
        int rr = i8 >> 5, c8 = i8 & 31;
        *(uint4*)(Wsm + rr * WPAD + c8 * 8) = *(const uint4*)(g_WT2 + rr * U_ + c8 * 8);
    }
    for (int i2 = tid; i2 < 16 * U_ / 2; i2 += 512) {
        int m = i2 >> 7, u2 = i2 & 127;
        float2 v = *(const float2*)(h0in + (size_t)BS_ * U_ + (size_t)(m0 + m) * U_ + u2 * 2);
        *(__half2*)(hb0 + m * WPAD + u2 * 2) = __floats2half2_rn(v.x, v.y);
    }
    __syncthreads();

    const int lane = tid & 31, warp = tid >> 5;
    const int n0 = warp * 16;
    const uint32_t wbase = (uint32_t)__cvta_generic_to_shared(Wsm);
    const uint32_t hoff = ((lane & 15) * WPAD + (lane >> 4) * 8) * 2;
    const uint32_t hs0 = (uint32_t)__cvta_generic_to_shared(hb0);
    const uint32_t hs1 = (uint32_t)__cvta_generic_to_shared(hb1);
    const int r = lane >> 2;

    uint32_t Br[16][4];
#pragma unroll
    for (int ks = 0; ks < 16; ++ks)
        ldsm4(Br[ks][0], Br[ks][1], Br[ks][2], Br[ks][3],
              wbase + ((n0 + (lane & 15)) * WPAD + ks * 16 + (lane >> 4) * 8) * 2);

    for (int t = 0; t < T_; ++t) {
        __half2 zv[2][2];
#pragma unroll
        for (int j = 0; j < 2; ++j) {
            int col = n0 + j * 8 + (lane & 3) * 2;
            size_t base = ((size_t)t * BS_ + m0 + r) * U_ + col;
            zv[j][0] = *(const __half2*)(g_Z1h + base);
            zv[j][1] = *(const __half2*)(g_Z1h + base + 8 * U_);
        }
        uint32_t ha = ((t & 1) ? hs1 : hs0) + hoff;
        float acc[2][4] = {};
#pragma unroll
        for (int ks = 0; ks < 16; ++ks) {
            uint32_t a0, a1, a2, a3;
            ldsm4(a0, a1, a2, a3, ha + ks * 32);
            mma16816(acc[0], a0, a1, a2, a3, Br[ks][0], Br[ks][2]);
            mma16816(acc[1], a0, a1, a2, a3, Br[ks][1], Br[ks][3]);
        }
        __half* hn = (t & 1) ? hb0 : hb1;
#pragma unroll
        for (int j = 0; j < 2; ++j) {
            int col = n0 + j * 8 + (lane & 3) * 2;
            float2 za = __half22float2(zv[j][0]);
            float2 zb = __half22float2(zv[j][1]);
            float v0 = ftanh(acc[j][0] + za.x);
            float v1 = ftanh(acc[j][1] + za.y);
            float v2 = ftanh(acc[j][2] + zb.x);
            float v3 = ftanh(acc[j][3] + zb.y);
            *(__half2*)(hn + r * WPAD + col) = __floats2half2_rn(v0, v1);
            *(__half2*)(hn + (r + 8) * WPAD + col) = __floats2half2_rn(v2, v3);
            if (t == T_ - 1) {
                float w0 = __ldg(Wo + col), w1 = __ldg(Wo + col + 1);
                atomicAdd(&zs[r],     v0 * w0 + v1 * w1);
                atomicAdd(&zs[r + 8], v2 * w0 + v3 * w1);
            }
        }
        __syncthreads();
    }
    if (tid < 16) {
        float z = zs[tid] + bo[0];
        out[m0 + tid] = 1.0f / (1.0f + expf(-z));
    }
}

// ---------------- launcher ----------------
extern "C" void kernel_launch(void* const* d_in, const int* in_sizes, int n_in,
                              void* d_out, int out_size) {
    const int*   tokens = (const int*)  d_in[0];
    const float* emb    = (const float*)d_in[1];
    const float* Wx0    = (const float*)d_in[2];
    const float* Wx1    = (const float*)d_in[3];
    const float* Wh     = (const float*)d_in[4];
    const float* b      = (const float*)d_in[5];
    const float* h0     = (const float*)d_in[6];
    const float* Wo     = (const float*)d_in[7];
    const float* bo     = (const float*)d_in[8];
    float* out = (float*)d_out;

    const int smem_x0 = (256 * EPS_ + 16 * EPS_) * 2;
    const int smem_r  = (U_ * WPAD + 32 * WPAD) * 2;   // 152064
    cudaFuncSetAttribute(k_x0,  cudaFuncAttributeMaxDynamicSharedMemorySize, smem_x0);
    cudaFuncSetAttribute(k_r0f, cudaFuncAttributeMaxDynamicSharedMemorySize, smem_r);
    cudaFuncSetAttribute(k_r1,  cudaFuncAttributeMaxDynamicSharedMemorySize, smem_r);

    k_prep<<<(V_ * EP_ + 255) / 256, 256>>>(emb, Wx0, Wx1, Wh);
    dim3 g1(128, 8);
    k_x0<<<g1, 256, smem_x0>>>(tokens, b);
    k_r0f<<<128, 512, smem_r>>>(h0, b);
    k_r1<<<128, 512, smem_r>>>(h0, Wo, bo, out);
}

// round 7
// speedup vs baseline: 1.8504x; 1.0788x over previous
#include <cuda_runtime.h>
#include <cuda_fp16.h>
#include <math.h>
#include <stdint.h>

// dims: tokens [2048,80] i32, emb [10000,100] f32, Wx0 [100,256], Wx1 [256,256],
// Wh [2,256,256], b [2,256], h0 [2,2048,256], Wo [256,1], bo [1] -> out [2048,1] f32

#define T_ 80
#define BS_ 2048
#define U_ 256
#define E_ 100
#define EP_ 112
#define V_ 10000

#define WPAD 264      // smem k-stride for 256-wide (conflict-free ldmatrix)
#define EPS_ 120      // smem k-stride for 112-wide

// ---------------- scratch ----------------
__device__ __half g_emb16[V_ * EP_];
__device__ __half g_Wx0T[U_ * EP_];
__device__ __half g_WT0[U_ * U_];              // Wh0^T [n][k]
__device__ __half g_WT1[U_ * U_];              // Wx1^T [n][k]
__device__ __half g_WT2[U_ * U_];              // Wh1^T [n][k]
__device__ __half g_X0[(size_t)T_ * BS_ * U_];  // x@Wx0+b0 (fp16)
__device__ __half g_Z1h[(size_t)T_ * BS_ * U_]; // h0@Wx1+b1 (fp16)

// ---------------- helpers ----------------
__device__ __forceinline__ void ldsm4(uint32_t &r0, uint32_t &r1, uint32_t &r2,
                                      uint32_t &r3, uint32_t addr) {
    asm volatile("ldmatrix.sync.aligned.m8n8.x4.shared.b16 {%0,%1,%2,%3}, [%4];\n"
                 : "=r"(r0), "=r"(r1), "=r"(r2), "=r"(r3) : "r"(addr));
}

__device__ __forceinline__ void mma16816(float c[4], uint32_t a0, uint32_t a1,
                                         uint32_t a2, uint32_t a3,
                                         uint32_t b0, uint32_t b1) {
    asm volatile(
        "mma.sync.aligned.m16n8k16.row.col.f32.f16.f16.f32 "
        "{%0,%1,%2,%3},{%4,%5,%6,%7},{%8,%9},{%0,%1,%2,%3};\n"
        : "+f"(c[0]), "+f"(c[1]), "+f"(c[2]), "+f"(c[3])
        : "r"(a0), "r"(a1), "r"(a2), "r"(a3), "r"(b0), "r"(b1));
}

__device__ __forceinline__ float ftanh(float x) {
    float y;
    asm("tanh.approx.f32 %0, %1;" : "=f"(y) : "f"(x));
    return y;
}

// ---------------- K0: prep ----------------
__global__ void k_prep(const float* __restrict__ emb, const float* __restrict__ Wx0,
                       const float* __restrict__ Wx1, const float* __restrict__ Wh) {
    int i = blockIdx.x * 256 + threadIdx.x;
    if (i < V_ * EP_) {
        int v = i / EP_, e = i - v * EP_;
        g_emb16[i] = __float2half(e < E_ ? emb[v * E_ + e] : 0.0f);
    }
    if (i < U_ * U_) {
        int n = i >> 8, k = i & 255;
        g_WT0[i] = __float2half(Wh[k * U_ + n]);
        g_WT1[i] = __float2half(Wx1[k * U_ + n]);
        g_WT2[i] = __float2half(Wh[U_ * U_ + k * U_ + n]);
    }
    if (i < U_ * EP_) {
        int u = i / EP_, e = i - u * EP_;
        g_Wx0T[i] = __float2half(e < E_ ? Wx0[e * U_ + u] : 0.0f);
    }
}

// ---------------- K1: X0 = emb[tok] @ Wx0 + b0 ----------------
__global__ __launch_bounds__(256, 1) void k_x0(const int* __restrict__ tokens,
                                               const float* __restrict__ bias) {
    extern __shared__ __half sm[];
    __half* Wsm = sm;               // 256 x 120
    __half* Asm = sm + 256 * EPS_;  // 16 x 120
    const int tid = threadIdx.x;
    const int m0 = blockIdx.x * 16;
    for (int i8 = tid; i8 < U_ * EP_ / 8; i8 += 256) {
        int r = i8 / 14, c8 = i8 - r * 14;
        *(uint4*)(Wsm + r * EPS_ + c8 * 8) = *(const uint4*)(g_Wx0T + r * EP_ + c8 * 8);
    }
    __syncthreads();
    const int lane = tid & 31, warp = tid >> 5;
    const int n0 = warp * 32;
    const uint32_t a_off = (uint32_t)__cvta_generic_to_shared(Asm) +
                           ((lane & 15) * EPS_ + (lane >> 4) * 8) * 2;
    const uint32_t wbase = (uint32_t)__cvta_generic_to_shared(Wsm);
    const int r = lane >> 2;

    uint32_t Br[7][2][4];
#pragma unroll
    for (int ks = 0; ks < 7; ++ks)
#pragma unroll
        for (int p = 0; p < 2; ++p)
            ldsm4(Br[ks][p][0], Br[ks][p][1], Br[ks][p][2], Br[ks][p][3],
                  wbase + ((n0 + p * 16 + (lane & 15)) * EPS_ + ks * 16 +
                           (lane >> 4) * 8) * 2);

    for (int tt = 0; tt < 10; ++tt) {
        int t = blockIdx.y * 10 + tt;
        __syncthreads();
        if (tid < 224) {
            int m = tid / 14, c8 = tid - m * 14;
            int tok = tokens[(m0 + m) * T_ + t];
            *(uint4*)(Asm + m * EPS_ + c8 * 8) =
                *(const uint4*)(g_emb16 + (size_t)tok * EP_ + c8 * 8);
        }
        __syncthreads();
        float acc[4][4] = {};
#pragma unroll
        for (int ks = 0; ks < 7; ++ks) {
            uint32_t a0, a1, a2, a3;
            ldsm4(a0, a1, a2, a3, a_off + ks * 32);
            mma16816(acc[0], a0, a1, a2, a3, Br[ks][0][0], Br[ks][0][2]);
            mma16816(acc[1], a0, a1, a2, a3, Br[ks][0][1], Br[ks][0][3]);
            mma16816(acc[2], a0, a1, a2, a3, Br[ks][1][0], Br[ks][1][2]);
            mma16816(acc[3], a0, a1, a2, a3, Br[ks][1][1], Br[ks][1][3]);
        }
#pragma unroll
        for (int j = 0; j < 4; ++j) {
            int col = n0 + j * 8 + (lane & 3) * 2;
            float bi0 = bias[col], bi1 = bias[col + 1];
            size_t base = ((size_t)t * BS_ + m0 + r) * U_ + col;
            *(__half2*)(g_X0 + base) = __floats2half2_rn(acc[j][0] + bi0, acc[j][1] + bi1);
            *(__half2*)(g_X0 + base + 8 * U_) = __floats2half2_rn(acc[j][2] + bi0, acc[j][3] + bi1);
        }
    }
}

// ---------------- K2: fused layer-0 recurrence + Wx1 GEMM ----------------
// 256 thr, 8 warps x n32. B0 in regs; A-frags cached across GEMM2(t)/GEMM1(t+1).
__global__ __launch_bounds__(256, 1) void k_r0f(const float* __restrict__ h0in,
                                                const float* __restrict__ bias) {
    extern __shared__ __half sm[];
    __half* Wsm = sm;                   // 256 x 264 : Wh0T staged first, then Wx1T
    __half* hb0 = sm + U_ * WPAD;       // 16 x 264 double buffer
    __half* hb1 = hb0 + 16 * WPAD;
    const int tid = threadIdx.x;
    const int m0 = blockIdx.x * 16;
    const int lane = tid & 31, warp = tid >> 5;
    const int n0 = warp * 32;
    const uint32_t wbase = (uint32_t)__cvta_generic_to_shared(Wsm);
    const uint32_t hoff = ((lane & 15) * WPAD + (lane >> 4) * 8) * 2;
    const uint32_t hs0 = (uint32_t)__cvta_generic_to_shared(hb0);
    const uint32_t hs1 = (uint32_t)__cvta_generic_to_shared(hb1);
    const int r = lane >> 2;

    // stage Wh0T, init h state
    for (int i8 = tid; i8 < U_ * U_ / 8; i8 += 256) {
        int rr = i8 >> 5, c8 = i8 & 31;
        *(uint4*)(Wsm + rr * WPAD + c8 * 8) = *(const uint4*)(g_WT0 + rr * U_ + c8 * 8);
    }
    for (int i2 = tid; i2 < 16 * U_ / 2; i2 += 256) {
        int m = i2 >> 7, u2 = i2 & 127;
        float2 v = *(const float2*)(h0in + (size_t)(m0 + m) * U_ + u2 * 2);
        *(__half2*)(hb0 + m * WPAD + u2 * 2) = __floats2half2_rn(v.x, v.y);
    }
    __syncthreads();

    // B0 (Wh0T) fragments -> registers: 16 ks x 2 p x 4 = 128 regs
    uint32_t B0r[16][2][4];
#pragma unroll
    for (int ks = 0; ks < 16; ++ks)
#pragma unroll
        for (int p = 0; p < 2; ++p)
            ldsm4(B0r[ks][p][0], B0r[ks][p][1], B0r[ks][p][2], B0r[ks][p][3],
                  wbase + ((n0 + p * 16 + (lane & 15)) * WPAD + ks * 16 +
                           (lane >> 4) * 8) * 2);
    __syncthreads();
    // overwrite staging with Wx1T (B1, read from smem each step)
    for (int i8 = tid; i8 < U_ * U_ / 8; i8 += 256) {
        int rr = i8 >> 5, c8 = i8 & 31;
        *(uint4*)(Wsm + rr * WPAD + c8 * 8) = *(const uint4*)(g_WT1 + rr * U_ + c8 * 8);
    }
    float2 b1v[4];
#pragma unroll
    for (int j = 0; j < 4; ++j) {
        int col = n0 + j * 8 + (lane & 3) * 2;
        b1v[j] = make_float2(__ldg(bias + U_ + col), __ldg(bias + U_ + col + 1));
    }
    __syncthreads();

    // A-fragment cache: h_{t-1} frags, reused by GEMM1(t)
    uint32_t Ac[16][4];
#pragma unroll
    for (int ks = 0; ks < 16; ++ks)
        ldsm4(Ac[ks][0], Ac[ks][1], Ac[ks][2], Ac[ks][3], hs0 + hoff + ks * 32);

    for (int t = 0; t < T_; ++t) {
        // prefetch X0[t]
        __half2 x0v[4][2];
#pragma unroll
        for (int j = 0; j < 4; ++j) {
            int col = n0 + j * 8 + (lane & 3) * 2;
            size_t base = ((size_t)t * BS_ + m0 + r) * U_ + col;
            x0v[j][0] = *(const __half2*)(g_X0 + base);
            x0v[j][1] = *(const __half2*)(g_X0 + base + 8 * U_);
        }
        // GEMM1: h_{t-1} @ Wh0 (A cached, B in regs)
        float acc[4][4] = {};
#pragma unroll
        for (int ks = 0; ks < 16; ++ks) {
            mma16816(acc[0], Ac[ks][0], Ac[ks][1], Ac[ks][2], Ac[ks][3],
                     B0r[ks][0][0], B0r[ks][0][2]);
            mma16816(acc[1], Ac[ks][0], Ac[ks][1], Ac[ks][2], Ac[ks][3],
                     B0r[ks][0][1], B0r[ks][0][3]);
            mma16816(acc[2], Ac[ks][0], Ac[ks][1], Ac[ks][2], Ac[ks][3],
                     B0r[ks][1][0], B0r[ks][1][2]);
            mma16816(acc[3], Ac[ks][0], Ac[ks][1], Ac[ks][2], Ac[ks][3],
                     B0r[ks][1][1], B0r[ks][1][3]);
        }
        // epilogue: tanh -> h_t into alternate buffer
        __half* hn = (t & 1) ? hb0 : hb1;
        const uint32_t hns = (t & 1) ? hs0 : hs1;
#pragma unroll
        for (int j = 0; j < 4; ++j) {
            int col = n0 + j * 8 + (lane & 3) * 2;
            float2 xa = __half22float2(x0v[j][0]);
            float2 xb = __half22float2(x0v[j][1]);
            *(__half2*)(hn + r * WPAD + col) =
                __floats2half2_rn(ftanh(acc[j][0] + xa.x), ftanh(acc[j][1] + xa.y));
            *(__half2*)(hn + (r + 8) * WPAD + col) =
                __floats2half2_rn(ftanh(acc[j][2] + xb.x), ftanh(acc[j][3] + xb.y));
        }
        __syncthreads();

        // reload A-frag cache from h_t (used by GEMM2 now and GEMM1 next step)
#pragma unroll
        for (int ks = 0; ks < 16; ++ks)
            ldsm4(Ac[ks][0], Ac[ks][1], Ac[ks][2], Ac[ks][3], hns + hoff + ks * 32);

        // GEMM2: h_t @ Wx1 + b1 -> Z1[t] (fp16 gmem), B1 streamed from smem
        float zac[4][4] = {};
#pragma unroll
        for (int ks = 0; ks < 16; ++ks) {
            uint32_t b0, b1_, b2, b3;
            ldsm4(b0, b1_, b2, b3,
                  wbase + ((n0 + (lane & 15)) * WPAD + ks * 16 + (lane >> 4) * 8) * 2);
            mma16816(zac[0], Ac[ks][0], Ac[ks][1], Ac[ks][2], Ac[ks][3], b0, b2);
            mma16816(zac[1], Ac[ks][0], Ac[ks][1], Ac[ks][2], Ac[ks][3], b1_, b3);
            ldsm4(b0, b1_, b2, b3,
                  wbase + ((n0 + 16 + (lane & 15)) * WPAD + ks * 16 + (lane >> 4) * 8) * 2);
            mma16816(zac[2], Ac[ks][0], Ac[ks][1], Ac[ks][2], Ac[ks][3], b0, b2);
            mma16816(zac[3], Ac[ks][0], Ac[ks][1], Ac[ks][2], Ac[ks][3], b1_, b3);
        }
#pragma unroll
        for (int j = 0; j < 4; ++j) {
            int col = n0 + j * 8 + (lane & 3) * 2;
            size_t base = ((size_t)t * BS_ + m0 + r) * U_ + col;
            *(__half2*)(g_Z1h + base) =
                __floats2half2_rn(zac[j][0] + b1v[j].x, zac[j][1] + b1v[j].y);
            *(__half2*)(g_Z1h + base + 8 * U_) =
                __floats2half2_rn(zac[j][2] + b1v[j].x, zac[j][3] + b1v[j].y);
        }
    }
}

// ---------------- K3: layer-1 recurrence + fused head (256 thr, 8 warps x n32) ----------------
__global__ __launch_bounds__(256, 1) void k_r1(const float* __restrict__ h0in,
                                               const float* __restrict__ Wo,
                                               const float* __restrict__ bo,
                                               float* __restrict__ out) {
    extern __shared__ __half sm[];
    __half* Wsm = sm;
    __half* hb0 = sm + U_ * WPAD;
    __half* hb1 = hb0 + 16 * WPAD;
    __shared__ float zs[16];
    const int tid = threadIdx.x;
    const int m0 = blockIdx.x * 16;
    if (tid < 16) zs[tid] = 0.0f;
    for (int i8 = tid; i8 < U_ * U_ / 8; i8 += 256) {
        int rr = i8 >> 5, c8 = i8 & 31;
        *(uint4*)(Wsm + rr * WPAD + c8 * 8) = *(const uint4*)(g_WT2 + rr * U_ + c8 * 8);
    }
    for (int i2 = tid; i2 < 16 * U_ / 2; i2 += 256) {
        int m = i2 >> 7, u2 = i2 & 127;
        float2 v = *(const float2*)(h0in + (size_t)BS_ * U_ + (size_t)(m0 + m) * U_ + u2 * 2);
        *(__half2*)(hb0 + m * WPAD + u2 * 2) = __floats2half2_rn(v.x, v.y);
    }
    __syncthreads();

    const int lane = tid & 31, warp = tid >> 5;
    const int n0 = warp * 32;
    const uint32_t wbase = (uint32_t)__cvta_generic_to_shared(Wsm);
    const uint32_t hoff = ((lane & 15) * WPAD + (lane >> 4) * 8) * 2;
    const uint32_t hs0 = (uint32_t)__cvta_generic_to_shared(hb0);
    const uint32_t hs1 = (uint32_t)__cvta_generic_to_shared(hb1);
    const int r = lane >> 2;

    uint32_t Br[16][2][4];
#pragma unroll
    for (int ks = 0; ks < 16; ++ks)
#pragma unroll
        for (int p = 0; p < 2; ++p)
            ldsm4(Br[ks][p][0], Br[ks][p][1], Br[ks][p][2], Br[ks][p][3],
                  wbase + ((n0 + p * 16 + (lane & 15)) * WPAD + ks * 16 +
                           (lane >> 4) * 8) * 2);

    for (int t = 0; t < T_; ++t) {
        __half2 zv[4][2];
#pragma unroll
        for (int j = 0; j < 4; ++j) {
            int col = n0 + j * 8 + (lane & 3) * 2;
            size_t base = ((size_t)t * BS_ + m0 + r) * U_ + col;
            zv[j][0] = *(const __half2*)(g_Z1h + base);
            zv[j][1] = *(const __half2*)(g_Z1h + base + 8 * U_);
        }
        uint32_t ha = ((t & 1) ? hs1 : hs0) + hoff;
        float acc[4][4] = {};
#pragma unroll
        for (int ks = 0; ks < 16; ++ks) {
            uint32_t a0, a1, a2, a3;
            ldsm4(a0, a1, a2, a3, ha + ks * 32);
            mma16816(acc[0], a0, a1, a2, a3, Br[ks][0][0], Br[ks][0][2]);
            mma16816(acc[1], a0, a1, a2, a3, Br[ks][0][1], Br[ks][0][3]);
            mma16816(acc[2], a0, a1, a2, a3, Br[ks][1][0], Br[ks][1][2]);
            mma16816(acc[3], a0, a1, a2, a3, Br[ks][1][1], Br[ks][1][3]);
        }
        __half* hn = (t & 1) ? hb0 : hb1;
#pragma unroll
        for (int j = 0; j < 4; ++j) {
            int col = n0 + j * 8 + (lane & 3) * 2;
            float2 za = __half22float2(zv[j][0]);
            float2 zb = __half22float2(zv[j][1]);
            float v0 = ftanh(acc[j][0] + za.x);
            float v1 = ftanh(acc[j][1] + za.y);
            float v2 = ftanh(acc[j][2] + zb.x);
            float v3 = ftanh(acc[j][3] + zb.y);
            *(__half2*)(hn + r * WPAD + col) = __floats2half2_rn(v0, v1);
            *(__half2*)(hn + (r + 8) * WPAD + col) = __floats2half2_rn(v2, v3);
            if (t == T_ - 1) {
                float w0 = __ldg(Wo + col), w1 = __ldg(Wo + col + 1);
                atomicAdd(&zs[r],     v0 * w0 + v1 * w1);
                atomicAdd(&zs[r + 8], v2 * w0 + v3 * w1);
            }
        }
        __syncthreads();
    }
    if (tid < 16) {
        float z = zs[tid] + bo[0];
        out[m0 + tid] = 1.0f / (1.0f + expf(-z));
    }
}

// ---------------- launcher ----------------
extern "C" void kernel_launch(void* const* d_in, const int* in_sizes, int n_in,
                              void* d_out, int out_size) {
    const int*   tokens = (const int*)  d_in[0];
    const float* emb    = (const float*)d_in[1];
    const float* Wx0    = (const float*)d_in[2];
    const float* Wx1    = (const float*)d_in[3];
    const float* Wh     = (const float*)d_in[4];
    const float* b      = (const float*)d_in[5];
    const float* h0     = (const float*)d_in[6];
    const float* Wo     = (const float*)d_in[7];
    const float* bo     = (const float*)d_in[8];
    float* out = (float*)d_out;

    const int smem_x0 = (256 * EPS_ + 16 * EPS_) * 2;
    const int smem_r  = (U_ * WPAD + 32 * WPAD) * 2;   // 152064
    cudaFuncSetAttribute(k_x0,  cudaFuncAttributeMaxDynamicSharedMemorySize, smem_x0);
    cudaFuncSetAttribute(k_r0f, cudaFuncAttributeMaxDynamicSharedMemorySize, smem_r);
    cudaFuncSetAttribute(k_r1,  cudaFuncAttributeMaxDynamicSharedMemorySize, smem_r);

    k_prep<<<(V_ * EP_ + 255) / 256, 256>>>(emb, Wx0, Wx1, Wh);
    dim3 g1(128, 8);
    k_x0<<<g1, 256, smem_x0>>>(tokens, b);
    k_r0f<<<128, 256, smem_r>>>(h0, b);
    k_r1<<<128, 256, smem_r>>>(h0, Wo, bo, out);
}